// round 16
// baseline (speedup 1.0000x reference)
#include <cuda_runtime.h>
#include <cuda_bf16.h>
#include <cstdint>

#define B_   32
#define CIN  256
#define COUT 256
#define H_   56
#define W_   56
#define PX   (H_ * W_)        // 3136
#define NTILE 128             // px per CTA
#define NTILES 25             // ceil(3136/128)

// ---------- static scratch ----------
__device__ __align__(16) int8_t g_x1[(size_t)B_ * PX * CIN];  // NHWC digit1
__device__ __align__(16) int8_t g_x2[(size_t)B_ * PX * CIN];  // NHWC digit2
__device__ __align__(16) int8_t g_x3[(size_t)B_ * PX * CIN];  // NHWC digit3
// A tiles: [tap][icp][mh][row 0..127][128 ic] s8, rows 128B, pre-swizzled, 16KB each
__device__ __align__(16) int8_t g_A[9 * 2 * 2 * 128 * 128];
__device__ float g_scale[COUT];   // inv/15
__device__ float g_bias[COUT];
__device__ unsigned g_maxw;
__device__ unsigned g_maxx;

// ---------- helpers ----------
__device__ __forceinline__ uint32_t smem_u32(const void* p) {
    uint32_t a;
    asm("{ .reg .u64 t; cvta.to.shared.u64 t, %1; cvt.u32.u64 %0, t; }" : "=r"(a) : "l"(p));
    return a;
}
__device__ __forceinline__ void cp16ca(uint32_t s, const void* g, uint32_t bytes) {
    asm volatile("cp.async.ca.shared.global [%0], [%1], 16, %2;"
                 :: "r"(s), "l"(g), "r"(bytes) : "memory");
}
__device__ __forceinline__ void cp16cg(uint32_t s, const void* g) {
    asm volatile("cp.async.cg.shared.global [%0], [%1], 16;"
                 :: "r"(s), "l"(g) : "memory");
}
#define CP_COMMIT() asm volatile("cp.async.commit_group;" ::: "memory")
#define CP_WAIT(n)  asm volatile("cp.async.wait_group %0;" :: "n"(n) : "memory")

__device__ __forceinline__ void ldsm4(uint32_t& r0, uint32_t& r1, uint32_t& r2, uint32_t& r3, uint32_t a) {
    asm volatile("ldmatrix.sync.aligned.m8n8.x4.shared.b16 {%0,%1,%2,%3}, [%4];"
                 : "=r"(r0), "=r"(r1), "=r"(r2), "=r"(r3) : "r"(a));
}
__device__ __forceinline__ void imma16832(int* c, const uint32_t* a, uint32_t b0, uint32_t b1) {
    asm volatile("mma.sync.aligned.m16n8k32.row.col.s32.s8.s8.s32 "
                 "{%0,%1,%2,%3}, {%4,%5,%6,%7}, {%8,%9}, {%0,%1,%2,%3};"
                 : "+r"(c[0]), "+r"(c[1]), "+r"(c[2]), "+r"(c[3])
                 : "r"(a[0]), "r"(a[1]), "r"(a[2]), "r"(a[3]), "r"(b0), "r"(b1));
}

// ---------- prep kernels ----------
__global__ void k_init() { if (threadIdx.x == 0) { g_maxw = 0u; g_maxx = 0u; } }

__global__ void k_maxred(const float* __restrict__ p, int n, unsigned* dst) {
    __shared__ float s[256];
    float m = 0.f;
    for (int i = blockIdx.x * blockDim.x + threadIdx.x; i < n; i += gridDim.x * blockDim.x)
        m = fmaxf(m, fabsf(p[i]));
    s[threadIdx.x] = m;
    __syncthreads();
    for (int o = 128; o > 0; o >>= 1) {
        if (threadIdx.x < o) s[threadIdx.x] = fmaxf(s[threadIdx.x], s[threadIdx.x + o]);
        __syncthreads();
    }
    if (threadIdx.x == 0) atomicMax(dst, __float_as_uint(s[0]));
}

__global__ void k_bn(const float* __restrict__ gamma, const float* __restrict__ beta,
                     const float* __restrict__ mean, const float* __restrict__ var) {
    int i = threadIdx.x;
    if (i < COUT) {
        float inv = gamma[i] / sqrtf(var[i] + 1e-5f);
        g_scale[i] = inv * (1.f / 15.f);
        g_bias[i]  = beta[i] - mean[i] * inv;
    }
}

// weights -> integer m = 2k-15 (s8 exact), pre-swizzled 16KB A tiles (128-ic rows)
__global__ void k_prepw(const float* __restrict__ w) {
    int idx = blockIdx.x * blockDim.x + threadIdx.x;
    if (idx >= COUT * CIN * 9) return;
    float T = tanhf(__uint_as_float(g_maxw));
    int oc  = idx / (CIN * 9);
    int rem = idx - oc * (CIN * 9);
    int ic  = rem / 9;
    int tap = rem - ic * 9;
    float t = tanhf(w[idx]);
    float k = rintf((t / (2.f * T) + 0.5f) * 15.f);   // 0..15
    int m = 2 * (int)k - 15;                           // odd int, |m|<=15
    int icp = ic >> 7, icc = ic & 127;
    int mh = oc >> 7, row = oc & 127;
    int tile = (tap * 2 + icp) * 2 + mh;
    int unit = (icc >> 4) ^ (row & 7);
    g_A[tile * 16384 + row * 128 + unit * 16 + (icc & 15)] = (int8_t)m;
}

// NCHW fp32 -> NHWC s8 digits d1, d2, d3 (base-254 signed decomposition)
__global__ void k_prepx(const float* __restrict__ x) {
    __shared__ float s[64][57];
    int y = blockIdx.x, b = blockIdx.y;
    int tid = threadIdx.x;
    const float s1 = __uint_as_float(g_maxx) * (1.f / 127.49f);
    const float s2 = s1 * (1.f / 254.f);
    const float s3 = s2 * (1.f / 254.f);
    const float is1 = 1.f / s1, is2 = 1.f / s2, is3 = 1.f / s3;
    for (int ch = 0; ch < 4; ++ch) {
        for (int i = tid; i < 64 * 56; i += 256) {
            int ic = i / 56, xx = i - ic * 56;
            s[ic][xx] = x[(((size_t)b * CIN + ch * 64 + ic) * H_ + y) * W_ + xx];
        }
        __syncthreads();
        for (int i = tid; i < 56 * 64; i += 256) {
            int xx = i >> 6, ic = i & 63;
            float v = s[ic][xx];
            float d1 = rintf(v * is1);
            float r  = v - d1 * s1;
            float d2 = fminf(fmaxf(rintf(r * is2), -127.f), 127.f);
            r = r - d2 * s2;
            float d3 = fminf(fmaxf(rintf(r * is3), -127.f), 127.f);
            size_t dst = (((size_t)b * H_ + y) * W_ + xx) * CIN + ch * 64 + ic;
            g_x1[dst] = (int8_t)(int)d1;
            g_x2[dst] = (int8_t)(int)d2;
            g_x3[dst] = (int8_t)(int)d3;
        }
        __syncthreads();
    }
}

// ---------- conv: IMMA s8, 3 sequential digit passes, 8 warps x (64x32) ----------
// smem: A0 @0, A1 @16K, B0 @32K, B1 @48K (all 128 rows x 128B, swizzled)
#define SA0 0
#define SA1 16384
#define SB0 32768
#define SB1 49152
#define SM_TOT 65536

__global__ __launch_bounds__(256, 1)
void k_conv(const float* __restrict__ alpha, float* __restrict__ out) {
    extern __shared__ char smem[];
    const uint32_t sb = smem_u32(smem);
    const int tid = threadIdx.x, wid = tid >> 5, lane = tid & 31;
    const int tile = blockIdx.x;           // n tile (0..24)
    const int mh   = blockIdx.y;           // 0..1
    const int b    = blockIdx.z;
    const int wm = wid >> 2;               // 0..1 -> m offset 64*wm
    const int wn = wid & 3;                // 0..3 -> n offset 32*wn

    const uint32_t aoff[2] = {SA0, SA1};
    const uint32_t boff[2] = {SB0, SB1};

    const float s1 = __uint_as_float(g_maxx) * (1.f / 127.49f);
    const float sd[3] = {s1, s1 * (1.f / 254.f), s1 * (1.f / (254.f * 254.f))};
    const int8_t* const xd[3] = {g_x1, g_x2, g_x3};

    // global stage g = digit*18 + s; s -> tap = s>>1, icp = s&1
    auto prefetch = [&](int g) {
        const int digit = g / 18, s = g - digit * 18;
        const int tap = s >> 1, icp = s & 1;
        {   // stage A: 16KB linear copy of pre-swizzled tile (1024 units, 4/thread)
            const char* Asrc = (const char*)g_A + (size_t)((tap * 2 + icp) * 2 + mh) * 16384;
            uint32_t Ad = sb + aoff[g & 1];
            #pragma unroll
            for (int j = 0; j < 4; ++j) {
                int idx = tid + j * 256;
                cp16cg(Ad + idx * 16, Asrc + idx * 16);
            }
        }
        {   // stage B: 128 px rows x 128B (128 ic s8), swizzled, zfill OOB
            const int dy = tap / 3 - 1, dx = tap % 3 - 1;
            const int8_t* xs = xd[digit];
            uint32_t Bd = sb + boff[g & 1];
            #pragma unroll
            for (int j = 0; j < 4; ++j) {
                int idx = tid + j * 256;          // 0..1023 16B units
                int row = idx >> 3, q = idx & 7;
                int px = tile * NTILE + row;
                int y = px / 56, xx = px - y * 56;
                int gy = y + dy, gx = xx + dx;
                bool ok = (px < PX) && ((unsigned)gy < (unsigned)H_) && ((unsigned)gx < (unsigned)W_);
                const int8_t* src = ok
                    ? xs + ((((size_t)b * H_ + gy) * W_ + gx) * CIN + icp * 128 + q * 16)
                    : xs;
                cp16ca(Bd + row * 128 + ((q ^ (row & 7)) * 16), src, ok ? 16u : 0u);
            }
        }
        CP_COMMIT();
    };

    float facc[4][4][4];
    int   iacc[4][4][4];
    #pragma unroll
    for (int i = 0; i < 4; ++i)
        #pragma unroll
        for (int jj = 0; jj < 4; ++jj)
            #pragma unroll
            for (int kq = 0; kq < 4; ++kq) { facc[i][jj][kq] = 0.f; iacc[i][jj][kq] = 0; }

    prefetch(0);

    const int lrow = lane & 15;
    const int lkh  = lane >> 4;

    for (int g = 0; g < 54; ++g) {
        if (g + 1 < 54) { prefetch(g + 1); CP_WAIT(1); }
        else            { CP_WAIT(0); }
        __syncthreads();

        const uint32_t Ab = sb + aoff[g & 1];
        const uint32_t Bb = sb + boff[g & 1];

        #pragma unroll
        for (int ks = 0; ks < 4; ++ks) {       // 4 k32 steps over 128 ic
            const int qbase = ks * 2 + lkh;
            uint32_t a[4][4];
            #pragma unroll
            for (int mt = 0; mt < 4; ++mt) {
                int r = wm * 64 + mt * 16 + lrow;
                ldsm4(a[mt][0], a[mt][1], a[mt][2], a[mt][3],
                      Ab + r * 128 + ((qbase ^ (r & 7)) * 16));
            }
            uint32_t br[2][4];
            #pragma unroll
            for (int bt = 0; bt < 2; ++bt) {
                int r = wn * 32 + bt * 16 + lrow;
                ldsm4(br[bt][0], br[bt][1], br[bt][2], br[bt][3],
                      Bb + r * 128 + ((qbase ^ (r & 7)) * 16));
            }
            #pragma unroll
            for (int mt = 0; mt < 4; ++mt) {
                #pragma unroll
                for (int bt = 0; bt < 2; ++bt) {
                    imma16832(iacc[mt][bt * 2 + 0], a[mt], br[bt][0], br[bt][2]);
                    imma16832(iacc[mt][bt * 2 + 1], a[mt], br[bt][1], br[bt][3]);
                }
            }
        }
        // digit pass boundary: fold int acc into fp32 acc and rezero
        if (g == 17 || g == 35 || g == 53) {
            const float sc = sd[g / 18];
            #pragma unroll
            for (int mt = 0; mt < 4; ++mt)
                #pragma unroll
                for (int nt = 0; nt < 4; ++nt)
                    #pragma unroll
                    for (int kq = 0; kq < 4; ++kq) {
                        facc[mt][nt][kq] = fmaf(sc, (float)iacc[mt][nt][kq], facc[mt][nt][kq]);
                        iacc[mt][nt][kq] = 0;
                    }
        }
        __syncthreads();
    }

    // ---------- epilogue: BN + PACT, fp32 stores ----------
    const float av = alpha[0];
    const float istep = 15.f / av, step = av / 15.f;
    #pragma unroll
    for (int mt = 0; mt < 4; ++mt) {
        const int r0 = wm * 64 + mt * 16 + (lane >> 2);
        #pragma unroll
        for (int half = 0; half < 2; ++half) {
            const int oc = mh * 128 + r0 + half * 8;
            const float sc = g_scale[oc], bi = g_bias[oc];
            float* ob = out + ((size_t)b * COUT + oc) * PX;
            #pragma unroll
            for (int nt = 0; nt < 4; ++nt) {
                const int px = tile * NTILE + wn * 32 + nt * 8 + (lane & 3) * 2;
                float f0 = facc[mt][nt][half * 2 + 0];
                float f1 = facc[mt][nt][half * 2 + 1];
                if (px + 1 < PX) {
                    float y0 = f0 * sc + bi;
                    float y1 = f1 * sc + bi;
                    y0 = fminf(fmaxf(y0, 0.f), av);
                    y1 = fminf(fmaxf(y1, 0.f), av);
                    float2 v = make_float2(rintf(y0 * istep) * step, rintf(y1 * istep) * step);
                    *(float2*)(ob + px) = v;
                } else if (px < PX) {
                    float y0 = f0 * sc + bi;
                    y0 = fminf(fmaxf(y0, 0.f), av);
                    ob[px] = rintf(y0 * istep) * step;
                }
            }
        }
    }
}

extern "C" void kernel_launch(void* const* d_in, const int* in_sizes, int n_in,
                              void* d_out, int out_size) {
    const float* x      = (const float*)d_in[0];
    const float* weight = (const float*)d_in[1];
    const float* gamma  = (const float*)d_in[2];
    const float* beta   = (const float*)d_in[3];
    const float* mean   = (const float*)d_in[4];
    const float* var    = (const float*)d_in[5];
    const float* alpha  = (const float*)d_in[6];
    float* out = (float*)d_out;

    unsigned* maxw; cudaGetSymbolAddress((void**)&maxw, g_maxw);
    unsigned* maxx; cudaGetSymbolAddress((void**)&maxx, g_maxx);

    k_init<<<1, 32>>>();
    k_bn<<<1, 256>>>(gamma, beta, mean, var);
    k_maxred<<<576, 256>>>(weight, COUT * CIN * 9, maxw);
    k_maxred<<<2048, 256>>>(x, B_ * CIN * PX, maxx);
    k_prepw<<<(COUT * CIN * 9 + 255) / 256, 256>>>(weight);
    k_prepx<<<dim3(H_, B_), 256>>>(x);

    cudaFuncSetAttribute(k_conv, cudaFuncAttributeMaxDynamicSharedMemorySize, SM_TOT);
    k_conv<<<dim3(NTILES, 2, B_), 256, SM_TOT>>>(alpha, out);
    (void)in_sizes; (void)n_in; (void)out_size;
}